// round 3
// baseline (speedup 1.0000x reference)
#include <cuda_runtime.h>
#include <cuda_bf16.h>
#include <math.h>

#define B 512
#define S 64
#define KNB 8
#define D 16
#define NSTEPS 100
#define NUNITS 128

#define BS   (B*S)        // 32768
#define BSN  (BS*KNB)     // 262144

// ---- device scratch (static, allocation-free) ----
__device__ float g_urel[B * 64];
__device__ int   g_e1[BSN];
__device__ int   g_r0[BSN];
__device__ float g_ev0[BS * D];
__device__ float g_ev1[BSN * D];
__device__ float g_tmp1[BSN * D];
__device__ float g_item[BS * D];

// ---------------------------------------------------------------------------
// K1: hop-0 adjacency gather + ev0 gather + urel precompute.
// grid covers BS*8 threads.
// ---------------------------------------------------------------------------
__global__ __launch_bounds__(256) void k1_kernel(
    const int* __restrict__ click_seq,
    const int* __restrict__ adj_ent, const int* __restrict__ adj_rel,
    const float* __restrict__ ent_emb,
    const float* __restrict__ usr_emb, const float* __restrict__ rel_emb,
    const int* __restrict__ u)
{
    int gt = blockIdx.x * blockDim.x + threadIdx.x;
    if (gt < BSN) {
        int bs = gt >> 3, j = gt & 7;
        int e0 = __ldg(click_seq + bs);
        g_e1[gt] = __ldg(adj_ent + (size_t)e0 * KNB + j);
        g_r0[gt] = __ldg(adj_rel + (size_t)e0 * KNB + j);
        if (j < 4) {
            float4 v = __ldg((const float4*)ent_emb + (size_t)e0 * 4 + j);
            ((float4*)g_ev0)[bs * 4 + j] = v;
        }
    }
    if (gt < B * 64) {
        int b = gt >> 6, r = gt & 63;
        const float* ur = usr_emb + (size_t)__ldg(u + b) * D;
        const float* rr = rel_emb + r * D;
        float s = 0.f;
#pragma unroll
        for (int d = 0; d < D; d++) s += __ldg(ur + d) * __ldg(rr + d);
        g_urel[gt] = s * (1.0f / 16.0f);
    }
}

// ---------------------------------------------------------------------------
// K3 (hot): one warp per (b,s,n). Gathers adj(e1), ev1, ev2; computes p1
// softmax in registers; writes tmp1 = ev1 + sum_k p1[k]*ev2[k], and ev1.
// grid = BSN warps (32768 blocks x 256 threads).
// ---------------------------------------------------------------------------
__global__ __launch_bounds__(256) void k3_kernel(
    const float* __restrict__ ent_emb,
    const int* __restrict__ adj_ent, const int* __restrict__ adj_rel)
{
    int warp = (blockIdx.x * blockDim.x + threadIdx.x) >> 5;
    int lane = threadIdx.x & 31;
    int bsn  = warp;                 // exactly BSN warps
    int k = lane >> 2, q = lane & 3; // k in [0,8), q = float4 quarter
    int b = bsn >> 9;                // bsn / (S*KNB)

    int e1 = __ldg(g_e1 + bsn);

    // hop-1 adjacency gather (4 lanes redundant per k -> coalesced 32B)
    int e2 = __ldg(adj_ent + (size_t)e1 * KNB + k);
    int r1 = __ldg(adj_rel + (size_t)e1 * KNB + k);

    // ev1 gather from lanes of k==0
    float4 ev1v = make_float4(0.f, 0.f, 0.f, 0.f);
    if (k == 0)
        ev1v = __ldg((const float4*)ent_emb + (size_t)e1 * 4 + q);

    // score + softmax over the 8 k-lanes (groups at stride 4: xor 4,8,16)
    float s = __ldg(g_urel + b * 64 + r1);
    float m = s;
    m = fmaxf(m, __shfl_xor_sync(0xffffffffu, m, 4));
    m = fmaxf(m, __shfl_xor_sync(0xffffffffu, m, 8));
    m = fmaxf(m, __shfl_xor_sync(0xffffffffu, m, 16));
    float e = expf(s - m);
    float sum = e;
    sum += __shfl_xor_sync(0xffffffffu, sum, 4);
    sum += __shfl_xor_sync(0xffffffffu, sum, 8);
    sum += __shfl_xor_sync(0xffffffffu, sum, 16);
    float w = e / sum;

    // the 128MB random gather: one float4 per lane (32 in flight per warp)
    float4 v = __ldg((const float4*)ent_emb + (size_t)e2 * 4 + q);
    float ax = w * v.x, ay = w * v.y, az = w * v.z, aw = w * v.w;

    // reduce over k (same-q groups)
#pragma unroll
    for (int msk = 4; msk <= 16; msk <<= 1) {
        ax += __shfl_xor_sync(0xffffffffu, ax, msk);
        ay += __shfl_xor_sync(0xffffffffu, ay, msk);
        az += __shfl_xor_sync(0xffffffffu, az, msk);
        aw += __shfl_xor_sync(0xffffffffu, aw, msk);
    }

    if (k == 0) {
        float4 t;
        t.x = ev1v.x + ax; t.y = ev1v.y + ay;
        t.z = ev1v.z + az; t.w = ev1v.w + aw;
        ((float4*)g_tmp1)[bsn * 4 + q] = t;
        ((float4*)g_ev1)[bsn * 4 + q]  = ev1v;
    }
}

// ---------------------------------------------------------------------------
// K4: per-(b,s) small MLP chain. All loads coalesced / cached.
// grid = BS, block = 128
// ---------------------------------------------------------------------------
__global__ __launch_bounds__(128) void k4_kernel(
    const float* __restrict__ agg_W, const float* __restrict__ agg_b)
{
    int bs = blockIdx.x;
    int tid = threadIdx.x;
    int b = bs >> 6;

    __shared__ float Wm[256], bb[16];
    __shared__ float tmp1[128], ev1s[128], ev0s[16];
    __shared__ float out1s[8][17];
    __shared__ float p0[8];

    Wm[tid]       = __ldg(agg_W + tid);
    Wm[tid + 128] = __ldg(agg_W + tid + 128);
    if (tid < 16) bb[tid] = __ldg(agg_b + tid);
    tmp1[tid] = g_tmp1[(size_t)bs * 128 + tid];
    ev1s[tid] = g_ev1[(size_t)bs * 128 + tid];
    if (tid < 16) ev0s[tid] = g_ev0[bs * 16 + tid];

    if (tid < 8) {
        float s = g_urel[b * 64 + g_r0[bs * 8 + tid]];
        float m = s;
        m = fmaxf(m, __shfl_xor_sync(0xffu, m, 1));
        m = fmaxf(m, __shfl_xor_sync(0xffu, m, 2));
        m = fmaxf(m, __shfl_xor_sync(0xffu, m, 4));
        float e = expf(s - m);
        float sum = e;
        sum += __shfl_xor_sync(0xffu, sum, 1);
        sum += __shfl_xor_sync(0xffu, sum, 2);
        sum += __shfl_xor_sync(0xffu, sum, 4);
        p0[tid] = e / sum;
    }
    __syncthreads();

    // hop1 linear + sigmoid: 128 outputs (n, dp)
    {
        int n = tid >> 4, dp = tid & 15;
        float a = bb[dp];
#pragma unroll
        for (int d = 0; d < 16; d++) a += tmp1[n * 16 + d] * Wm[d * 16 + dp];
        out1s[n][dp] = 1.f / (1.f + expf(-a));
    }
    __syncthreads();

    // hop0: i=0 then i=1, all in warp 0 lanes 0-15 with shuffles
    if (tid < 16) {
        float t0 = ev0s[tid];
#pragma unroll
        for (int k = 0; k < 8; k++) t0 += p0[k] * ev1s[k * 16 + tid];
        float a = bb[tid];
#pragma unroll
        for (int d = 0; d < 16; d++)
            a += __shfl_sync(0xffffu, t0, d) * Wm[d * 16 + tid];
        float o0 = 1.f / (1.f + expf(-a));

        float tf = o0;
#pragma unroll
        for (int k = 0; k < 8; k++) tf += p0[k] * out1s[k][tid];
        float a2 = bb[tid];
#pragma unroll
        for (int d = 0; d < 16; d++)
            a2 += __shfl_sync(0xffffu, tf, d) * Wm[d * 16 + tid];
        g_item[bs * 16 + tid] = fmaxf(tanhf(a2), 0.f);
    }
}

// ---------------------------------------------------------------------------
// final: per-batch S-reduction + fc head + diffusion MLP.
// grid=B, block=128
// ---------------------------------------------------------------------------
__global__ __launch_bounds__(128) void final_kernel(
    const float* __restrict__ usr_emb, const float* __restrict__ ent_emb,
    const float* __restrict__ fc1_W, const float* __restrict__ fc1_b,
    const float* __restrict__ fc2_W, const float* __restrict__ fc2_b,
    const float* __restrict__ W1, const float* __restrict__ b1,
    const float* __restrict__ W2, const float* __restrict__ b2,
    const float* __restrict__ W3, const float* __restrict__ b3,
    const float* __restrict__ W4, const float* __restrict__ b4,
    const float* __restrict__ se1, const float* __restrict__ se2,
    const float* __restrict__ se3,
    const float* __restrict__ noise_e,
    const int* __restrict__ u, const int* __restrict__ v,
    const int* __restrict__ t,
    float* __restrict__ out)
{
    int b = blockIdx.x;
    int tid = threadIdx.x;
    __shared__ float xs[16], h1[128], h2[128], h3[128];
    __shared__ float psum[8][16], pmax[8][16];
    __shared__ float fus[32], hh[64], prod[16];
    __shared__ float ab_sh, omb_sh;

    int tb = t[b];
    if (tid == 0) {
        float ap = 1.f;
        for (int i = 0; i <= tb; i++) {
            float z = -6.f + 12.f * (float)i / 99.f;
            float beta = (1.f / (1.f + expf(-z))) * (0.005f - 1e-5f) + 1e-5f;
            ap *= (1.f - beta);
        }
        ab_sh = sqrtf(ap);
        omb_sh = sqrtf(1.f - ap);
    }
    __syncthreads();
    float ab = ab_sh, omb = omb_sh;

    if (tid < 16)
        xs[tid] = usr_emb[(size_t)u[b] * D + tid] * ab + noise_e[b * D + tid] * omb;
    __syncthreads();

    {
        float a = b1[tid] + se1[tb * NUNITS + tid];
#pragma unroll
        for (int d = 0; d < 16; d++) a += xs[d] * W1[d * NUNITS + tid];
        h1[tid] = fmaxf(a, 0.f);
    }
    __syncthreads();
    {
        float a = b2[tid] + se2[tb * NUNITS + tid];
        for (int i = 0; i < 128; i++) a += h1[i] * W2[i * NUNITS + tid];
        h2[tid] = fmaxf(a, 0.f);
    }
    __syncthreads();
    {
        float a = b3[tid] + se3[tb * NUNITS + tid];
        for (int i = 0; i < 128; i++) a += h2[i] * W3[i * NUNITS + tid];
        h3[tid] = fmaxf(a, 0.f);
    }
    __syncthreads();
    if (tid < 16) {
        float a = b4[tid];
        for (int i = 0; i < 128; i++) a += h3[i] * W4[i * D + tid];
        out[b * (1 + D) + 1 + tid] = a;
    }

    {
        int d = tid & 15, sc = tid >> 4;
        float s = 0.f, m = -1e30f;
#pragma unroll
        for (int j = 0; j < 8; j++) {
            float vv = g_item[((size_t)b * S + sc * 8 + j) * D + d];
            s += vv;
            m = fmaxf(m, vv);
        }
        psum[sc][d] = s;
        pmax[sc][d] = m;
    }
    __syncthreads();
    if (tid < 16) {
        float s = 0.f, m = -1e30f;
#pragma unroll
        for (int c = 0; c < 8; c++) { s += psum[c][tid]; m = fmaxf(m, pmax[c][tid]); }
        fus[tid]      = fmaxf(s, 0.f);
        fus[16 + tid] = fmaxf(m, 0.f);
    }
    __syncthreads();

    if (tid < 64) {
        float a = fc1_b[tid];
#pragma unroll
        for (int i = 0; i < 32; i++) a += fus[i] * fc1_W[i * 64 + tid];
        hh[tid] = fmaxf(a, 0.f);
    }
    __syncthreads();
    if (tid < 16) {
        float a = fc2_b[tid];
#pragma unroll
        for (int i = 0; i < 64; i++) a += hh[i] * fc2_W[i * D + tid];
        float f = fmaxf(a, 0.f);
        prod[tid] = f * __ldg(ent_emb + (size_t)v[b] * D + tid);
    }
    __syncthreads();
    if (tid == 0) {
        float s = 0.f;
#pragma unroll
        for (int i = 0; i < 16; i++) s += prod[i];
        out[b * (1 + D)] = 1.f / (1.f + expf(-s));
    }
}

// ---------------------------------------------------------------------------
extern "C" void kernel_launch(void* const* d_in, const int* in_sizes, int n_in,
                              void* d_out, int out_size)
{
    const float* usr_emb  = (const float*)d_in[0];
    const float* ent_emb  = (const float*)d_in[1];
    const float* rel_emb  = (const float*)d_in[2];
    const float* agg_W    = (const float*)d_in[3];
    const float* agg_b    = (const float*)d_in[4];
    const float* fc1_W    = (const float*)d_in[5];
    const float* fc1_b    = (const float*)d_in[6];
    const float* fc2_W    = (const float*)d_in[7];
    const float* fc2_b    = (const float*)d_in[8];
    const float* mlp_W1   = (const float*)d_in[9];
    const float* mlp_b1   = (const float*)d_in[10];
    const float* mlp_W2   = (const float*)d_in[11];
    const float* mlp_b2   = (const float*)d_in[12];
    const float* mlp_W3   = (const float*)d_in[13];
    const float* mlp_b3   = (const float*)d_in[14];
    const float* mlp_W4   = (const float*)d_in[15];
    const float* mlp_b4   = (const float*)d_in[16];
    const float* se1      = (const float*)d_in[17];
    const float* se2      = (const float*)d_in[18];
    const float* se3      = (const float*)d_in[19];
    const float* noise_e  = (const float*)d_in[20];
    const int*   u        = (const int*)d_in[21];
    const int*   v        = (const int*)d_in[22];
    const int*   click    = (const int*)d_in[23];
    const int*   adj_ent  = (const int*)d_in[24];
    const int*   adj_rel  = (const int*)d_in[25];
    const int*   t        = (const int*)d_in[26];
    float* out = (float*)d_out;

    k1_kernel<<<(BSN + 255) / 256, 256>>>(click, adj_ent, adj_rel, ent_emb,
                                          usr_emb, rel_emb, u);
    k3_kernel<<<BSN / 8, 256>>>(ent_emb, adj_ent, adj_rel);
    k4_kernel<<<BS, 128>>>(agg_W, agg_b);
    final_kernel<<<B, 128>>>(usr_emb, ent_emb, fc1_W, fc1_b, fc2_W, fc2_b,
                             mlp_W1, mlp_b1, mlp_W2, mlp_b2, mlp_W3, mlp_b3,
                             mlp_W4, mlp_b4, se1, se2, se3, noise_e,
                             u, v, t, out);
}

// round 4
// speedup vs baseline: 1.6994x; 1.6994x over previous
#include <cuda_runtime.h>
#include <cuda_bf16.h>
#include <math.h>

#define B 512
#define S 64
#define KNB 8
#define D 16
#define NSTEPS 100
#define NUNITS 128

#define BS   (B*S)        // 32768
#define BSN  (BS*KNB)     // 262144

// ---- device scratch (static, allocation-free) ----
__device__ float g_urel[B * 64];
__device__ int   g_e1[BSN];
__device__ int   g_r0[BSN];
__device__ float g_ev0[BS * D];
__device__ int   g_e2[BSN * KNB];
__device__ float g_w [BSN * KNB];
__device__ float g_item[BS * D];
__device__ float g_ab[NSTEPS];
__device__ float g_omb[NSTEPS];

// ---------------------------------------------------------------------------
// K1: hop-0 adjacency gather + ev0 + urel + alpha schedule table.
// grid = BSN threads (1024 x 256)
// ---------------------------------------------------------------------------
__global__ __launch_bounds__(256) void k1_kernel(
    const int* __restrict__ click_seq,
    const int* __restrict__ adj_ent, const int* __restrict__ adj_rel,
    const float* __restrict__ ent_emb,
    const float* __restrict__ usr_emb, const float* __restrict__ rel_emb,
    const int* __restrict__ u)
{
    int tid = threadIdx.x;
    int gt = blockIdx.x * 256 + tid;

    if (gt < BSN) {
        int bs = gt >> 3, j = gt & 7;
        int e0 = __ldg(click_seq + bs);
        g_e1[gt] = __ldg(adj_ent + (size_t)e0 * KNB + j);
        g_r0[gt] = __ldg(adj_rel + (size_t)e0 * KNB + j);
        if (j < 4) {
            float4 v = __ldg((const float4*)ent_emb + (size_t)e0 * 4 + j);
            ((float4*)g_ev0)[bs * 4 + j] = v;
        }
    }
    if (gt < B * 64) {
        int b = gt >> 6, r = gt & 63;
        const float* ur = usr_emb + (size_t)__ldg(u + b) * D;
        const float* rr = rel_emb + r * D;
        float s = 0.f;
#pragma unroll
        for (int d = 0; d < D; d++) s += __ldg(ur + d) * __ldg(rr + d);
        g_urel[gt] = s * (1.0f / 16.0f);
    }
    // alpha schedule (block 0 only)
    if (blockIdx.x == 0) {
        __shared__ float betas[NSTEPS];
        if (tid < NSTEPS) {
            float z = -6.f + 12.f * (float)tid / 99.f;
            betas[tid] = (1.f / (1.f + expf(-z))) * (0.005f - 1e-5f) + 1e-5f;
        }
        __syncthreads();
        if (tid == 0) {
            float ap = 1.f;
            for (int i = 0; i < NSTEPS; i++) {
                ap *= (1.f - betas[i]);
                g_ab[i]  = sqrtf(ap);
                g_omb[i] = sqrtf(1.f - ap);
            }
        }
    }
}

// ---------------------------------------------------------------------------
// K2: thread per (bsn,k). Gathers adj(e1) rows, computes softmax weight w.
// grid = BSN*8 threads (8192 x 256)
// ---------------------------------------------------------------------------
__global__ __launch_bounds__(256) void k2_kernel(
    const int* __restrict__ adj_ent, const int* __restrict__ adj_rel)
{
    int gt = blockIdx.x * 256 + threadIdx.x;
    int bsn = gt >> 3, k = gt & 7;
    int b = bsn >> 9;                       // bsn / (S*KNB)

    int e1 = __ldg(g_e1 + bsn);
    int e2 = __ldg(adj_ent + (size_t)e1 * KNB + k);
    int r1 = __ldg(adj_rel + (size_t)e1 * KNB + k);

    float s = __ldg(g_urel + b * 64 + r1);
    float m = s;
    m = fmaxf(m, __shfl_xor_sync(0xffffffffu, m, 1));
    m = fmaxf(m, __shfl_xor_sync(0xffffffffu, m, 2));
    m = fmaxf(m, __shfl_xor_sync(0xffffffffu, m, 4));
    float e = expf(s - m);
    float sum = e;
    sum += __shfl_xor_sync(0xffffffffu, sum, 1);
    sum += __shfl_xor_sync(0xffffffffu, sum, 2);
    sum += __shfl_xor_sync(0xffffffffu, sum, 4);

    g_w[gt]  = e / sum;
    g_e2[gt] = e2;
}

// ---------------------------------------------------------------------------
// K3 (hot, fused): 256-thread block handles 8 (b,s) pairs end-to-end.
// Thread = (bsl, n, q): 9 independent random float4 loads in flight.
// grid = BS/8 = 4096 blocks.
// ---------------------------------------------------------------------------
__global__ __launch_bounds__(256) void k3_kernel(
    const float* __restrict__ ent_emb,
    const float* __restrict__ agg_W, const float* __restrict__ agg_b)
{
    __shared__ float Wm[256], bb[16];
    __shared__ float tmp1s[8][8][17];
    __shared__ float ev1s[8][8][17];
    __shared__ float out1s[8][8][17];
    __shared__ float ev0s[8][16];
    __shared__ float p0s[8][8];
    __shared__ float t0s[8][17];
    __shared__ float tfs[8][17];

    int tid = threadIdx.x;
    int bsl = tid >> 5, n = (tid >> 2) & 7, q = tid & 3;
    int bs  = blockIdx.x * 8 + bsl;
    int bsn = bs * KNB + n;
    int b   = bs >> 6;

    Wm[tid] = __ldg(agg_W + tid);
    if (tid < 16) bb[tid] = __ldg(agg_b + tid);

    // coalesced loads of e2 indices + weights (vectorized)
    int4   ea = __ldg((const int4*)g_e2 + bsn * 2);
    int4   eb = __ldg((const int4*)g_e2 + bsn * 2 + 1);
    float4 wa = __ldg((const float4*)g_w + bsn * 2);
    float4 wb = __ldg((const float4*)g_w + bsn * 2 + 1);
    int e1 = __ldg(g_e1 + bsn);

    // 9 independent random gathers
    const float4* E = (const float4*)ent_emb;
    float4 v0 = __ldg(E + (size_t)ea.x * 4 + q);
    float4 v1 = __ldg(E + (size_t)ea.y * 4 + q);
    float4 v2 = __ldg(E + (size_t)ea.z * 4 + q);
    float4 v3 = __ldg(E + (size_t)ea.w * 4 + q);
    float4 v4 = __ldg(E + (size_t)eb.x * 4 + q);
    float4 v5 = __ldg(E + (size_t)eb.y * 4 + q);
    float4 v6 = __ldg(E + (size_t)eb.z * 4 + q);
    float4 v7 = __ldg(E + (size_t)eb.w * 4 + q);
    float4 e1v = __ldg(E + (size_t)e1 * 4 + q);

    float4 acc;
    acc.x = wa.x*v0.x + wa.y*v1.x + wa.z*v2.x + wa.w*v3.x
          + wb.x*v4.x + wb.y*v5.x + wb.z*v6.x + wb.w*v7.x;
    acc.y = wa.x*v0.y + wa.y*v1.y + wa.z*v2.y + wa.w*v3.y
          + wb.x*v4.y + wb.y*v5.y + wb.z*v6.y + wb.w*v7.y;
    acc.z = wa.x*v0.z + wa.y*v1.z + wa.z*v2.z + wa.w*v3.z
          + wb.x*v4.z + wb.y*v5.z + wb.z*v6.z + wb.w*v7.z;
    acc.w = wa.x*v0.w + wa.y*v1.w + wa.z*v2.w + wa.w*v3.w
          + wb.x*v4.w + wb.y*v5.w + wb.z*v6.w + wb.w*v7.w;

    int qq = q * 4;
    tmp1s[bsl][n][qq+0] = e1v.x + acc.x;
    tmp1s[bsl][n][qq+1] = e1v.y + acc.y;
    tmp1s[bsl][n][qq+2] = e1v.z + acc.z;
    tmp1s[bsl][n][qq+3] = e1v.w + acc.w;
    ev1s[bsl][n][qq+0] = e1v.x;
    ev1s[bsl][n][qq+1] = e1v.y;
    ev1s[bsl][n][qq+2] = e1v.z;
    ev1s[bsl][n][qq+3] = e1v.w;

    // ev0 load
    if (tid < 128) {
        int bl = tid >> 4, d = tid & 15;
        ev0s[bl][d] = __ldg(g_ev0 + (size_t)(blockIdx.x * 8 + bl) * 16 + d);
    }

    // hop-0 softmax weights p0 (per warp = per bsl; q-invariant lanes)
    {
        int r0 = __ldg(g_r0 + bsn);
        float s = __ldg(g_urel + b * 64 + r0);
        float m = s;
        m = fmaxf(m, __shfl_xor_sync(0xffffffffu, m, 4));
        m = fmaxf(m, __shfl_xor_sync(0xffffffffu, m, 8));
        m = fmaxf(m, __shfl_xor_sync(0xffffffffu, m, 16));
        float e = expf(s - m);
        float sum = e;
        sum += __shfl_xor_sync(0xffffffffu, sum, 4);
        sum += __shfl_xor_sync(0xffffffffu, sum, 8);
        sum += __shfl_xor_sync(0xffffffffu, sum, 16);
        if (q == 0) p0s[bsl][n] = e / sum;
    }
    __syncthreads();

    // hop1 linear + sigmoid (4 outputs / thread) and t0 partial (tid<128)
#pragma unroll
    for (int j = 0; j < 4; j++) {
        int o = tid + 256 * j;
        int bl = o >> 7, n2 = (o >> 4) & 7, dp = o & 15;
        float a = bb[dp];
#pragma unroll
        for (int d = 0; d < 16; d++)
            a = fmaf(tmp1s[bl][n2][d], Wm[d * 16 + dp], a);
        out1s[bl][n2][dp] = 1.f / (1.f + expf(-a));
    }
    if (tid < 128) {
        int bl = tid >> 4, d = tid & 15;
        float t0 = ev0s[bl][d];
#pragma unroll
        for (int k = 0; k < 8; k++)
            t0 = fmaf(p0s[bl][k], ev1s[bl][k][d], t0);
        t0s[bl][d] = t0;
    }
    __syncthreads();

    if (tid < 128) {
        int bl = tid >> 4, d = tid & 15;
        float a = bb[d];
#pragma unroll
        for (int d2 = 0; d2 < 16; d2++)
            a = fmaf(t0s[bl][d2], Wm[d2 * 16 + d], a);
        float o0 = 1.f / (1.f + expf(-a));
        float tf = o0;
#pragma unroll
        for (int k = 0; k < 8; k++)
            tf = fmaf(p0s[bl][k], out1s[bl][k][d], tf);
        tfs[bl][d] = tf;
    }
    __syncthreads();

    if (tid < 128) {
        int bl = tid >> 4, d = tid & 15;
        float a = bb[d];
#pragma unroll
        for (int d2 = 0; d2 < 16; d2++)
            a = fmaf(tfs[bl][d2], Wm[d2 * 16 + d], a);
        g_item[(size_t)(blockIdx.x * 8 + bl) * 16 + d] = fmaxf(tanhf(a), 0.f);
    }
}

// ---------------------------------------------------------------------------
// final: per-batch S-reduction + fc head + diffusion MLP (ILP-optimized).
// grid=B, block=128
// ---------------------------------------------------------------------------
__global__ __launch_bounds__(128) void final_kernel(
    const float* __restrict__ usr_emb, const float* __restrict__ ent_emb,
    const float* __restrict__ fc1_W, const float* __restrict__ fc1_b,
    const float* __restrict__ fc2_W, const float* __restrict__ fc2_b,
    const float* __restrict__ W1, const float* __restrict__ b1,
    const float* __restrict__ W2, const float* __restrict__ b2,
    const float* __restrict__ W3, const float* __restrict__ b3,
    const float* __restrict__ W4, const float* __restrict__ b4,
    const float* __restrict__ se1, const float* __restrict__ se2,
    const float* __restrict__ se3,
    const float* __restrict__ noise_e,
    const int* __restrict__ u, const int* __restrict__ v,
    const int* __restrict__ t,
    float* __restrict__ out)
{
    int b = blockIdx.x;
    int tid = threadIdx.x;
    __shared__ float xs[16], h1[128], h2[128], h3[128];
    __shared__ float psum[8][16], pmax[8][16], p4[8][16];
    __shared__ float fus[32], hh[64], prod[16];

    int tb = __ldg(t + b);
    float ab  = __ldg(g_ab + tb);
    float omb = __ldg(g_omb + tb);

    if (tid < 16)
        xs[tid] = __ldg(usr_emb + (size_t)__ldg(u + b) * D + tid) * ab
                + __ldg(noise_e + b * D + tid) * omb;

    // --- item_emb reduction over S (do the global loads early, overlap MLP) ---
    {
        int d = tid & 15, sc = tid >> 4;
        float s = 0.f, m = -1e30f;
#pragma unroll
        for (int j = 0; j < 8; j++) {
            float vv = __ldg(g_item + ((size_t)b * S + sc * 8 + j) * D + d);
            s += vv;
            m = fmaxf(m, vv);
        }
        psum[sc][d] = s;
        pmax[sc][d] = m;
    }
    __syncthreads();

    // diffusion MLP layer 1 (16 -> 128)
    {
        float a = __ldg(b1 + tid) + __ldg(se1 + tb * NUNITS + tid);
#pragma unroll
        for (int d = 0; d < 16; d++) a = fmaf(xs[d], __ldg(W1 + d * NUNITS + tid), a);
        h1[tid] = fmaxf(a, 0.f);
    }
    __syncthreads();
    // layer 2 (128 -> 128), 4 independent accumulator chains
    {
        float a0 = 0.f, a1 = 0.f, a2 = 0.f, a3 = 0.f;
#pragma unroll
        for (int i = 0; i < 128; i += 4) {
            a0 = fmaf(h1[i+0], __ldg(W2 + (i+0) * NUNITS + tid), a0);
            a1 = fmaf(h1[i+1], __ldg(W2 + (i+1) * NUNITS + tid), a1);
            a2 = fmaf(h1[i+2], __ldg(W2 + (i+2) * NUNITS + tid), a2);
            a3 = fmaf(h1[i+3], __ldg(W2 + (i+3) * NUNITS + tid), a3);
        }
        float a = __ldg(b2 + tid) + __ldg(se2 + tb * NUNITS + tid)
                + ((a0 + a1) + (a2 + a3));
        h2[tid] = fmaxf(a, 0.f);
    }
    __syncthreads();
    // layer 3
    {
        float a0 = 0.f, a1 = 0.f, a2 = 0.f, a3 = 0.f;
#pragma unroll
        for (int i = 0; i < 128; i += 4) {
            a0 = fmaf(h2[i+0], __ldg(W3 + (i+0) * NUNITS + tid), a0);
            a1 = fmaf(h2[i+1], __ldg(W3 + (i+1) * NUNITS + tid), a1);
            a2 = fmaf(h2[i+2], __ldg(W3 + (i+2) * NUNITS + tid), a2);
            a3 = fmaf(h2[i+3], __ldg(W3 + (i+3) * NUNITS + tid), a3);
        }
        float a = __ldg(b3 + tid) + __ldg(se3 + tb * NUNITS + tid)
                + ((a0 + a1) + (a2 + a3));
        h3[tid] = fmaxf(a, 0.f);
    }
    __syncthreads();
    // layer 4 (128 -> 16) parallelized over all 128 threads
    {
        int d = tid & 15, g = tid >> 4;
        float a = 0.f;
#pragma unroll
        for (int i = 0; i < 16; i++)
            a = fmaf(h3[g * 16 + i], __ldg(W4 + (g * 16 + i) * D + d), a);
        p4[g][d] = a;
    }
    __syncthreads();
    if (tid < 16) {
        float a = __ldg(b4 + tid);
#pragma unroll
        for (int g = 0; g < 8; g++) a += p4[g][tid];
        out[b * (1 + D) + 1 + tid] = a;
    }

    // --- fusion head ---
    if (tid < 16) {
        float s = 0.f, m = -1e30f;
#pragma unroll
        for (int c = 0; c < 8; c++) { s += psum[c][tid]; m = fmaxf(m, pmax[c][tid]); }
        fus[tid]      = fmaxf(s, 0.f);
        fus[16 + tid] = fmaxf(m, 0.f);
    }
    __syncthreads();

    if (tid < 64) {
        float a = __ldg(fc1_b + tid);
#pragma unroll
        for (int i = 0; i < 32; i++) a = fmaf(fus[i], __ldg(fc1_W + i * 64 + tid), a);
        hh[tid] = fmaxf(a, 0.f);
    }
    __syncthreads();
    if (tid < 16) {
        float a = __ldg(fc2_b + tid);
#pragma unroll
        for (int i = 0; i < 64; i++) a = fmaf(hh[i], __ldg(fc2_W + i * D + tid), a);
        float f = fmaxf(a, 0.f);
        prod[tid] = f * __ldg(ent_emb + (size_t)__ldg(v + b) * D + tid);
    }
    __syncthreads();
    if (tid == 0) {
        float s = 0.f;
#pragma unroll
        for (int i = 0; i < 16; i++) s += prod[i];
        out[b * (1 + D)] = 1.f / (1.f + expf(-s));
    }
}

// ---------------------------------------------------------------------------
extern "C" void kernel_launch(void* const* d_in, const int* in_sizes, int n_in,
                              void* d_out, int out_size)
{
    const float* usr_emb  = (const float*)d_in[0];
    const float* ent_emb  = (const float*)d_in[1];
    const float* rel_emb  = (const float*)d_in[2];
    const float* agg_W    = (const float*)d_in[3];
    const float* agg_b    = (const float*)d_in[4];
    const float* fc1_W    = (const float*)d_in[5];
    const float* fc1_b    = (const float*)d_in[6];
    const float* fc2_W    = (const float*)d_in[7];
    const float* fc2_b    = (const float*)d_in[8];
    const float* mlp_W1   = (const float*)d_in[9];
    const float* mlp_b1   = (const float*)d_in[10];
    const float* mlp_W2   = (const float*)d_in[11];
    const float* mlp_b2   = (const float*)d_in[12];
    const float* mlp_W3   = (const float*)d_in[13];
    const float* mlp_b3   = (const float*)d_in[14];
    const float* mlp_W4   = (const float*)d_in[15];
    const float* mlp_b4   = (const float*)d_in[16];
    const float* se1      = (const float*)d_in[17];
    const float* se2      = (const float*)d_in[18];
    const float* se3      = (const float*)d_in[19];
    const float* noise_e  = (const float*)d_in[20];
    const int*   u        = (const int*)d_in[21];
    const int*   v        = (const int*)d_in[22];
    const int*   click    = (const int*)d_in[23];
    const int*   adj_ent  = (const int*)d_in[24];
    const int*   adj_rel  = (const int*)d_in[25];
    const int*   t        = (const int*)d_in[26];
    float* out = (float*)d_out;

    k1_kernel<<<(BSN + 255) / 256, 256>>>(click, adj_ent, adj_rel, ent_emb,
                                          usr_emb, rel_emb, u);
    k2_kernel<<<(BSN * KNB) / 256, 256>>>(adj_ent, adj_rel);
    k3_kernel<<<BS / 8, 256>>>(ent_emb, agg_W, agg_b);
    final_kernel<<<B, 128>>>(usr_emb, ent_emb, fc1_W, fc1_b, fc2_W, fc2_b,
                             mlp_W1, mlp_b1, mlp_W2, mlp_b2, mlp_W3, mlp_b3,
                             mlp_W4, mlp_b4, se1, se2, se3, noise_e,
                             u, v, t, out);
}

// round 5
// speedup vs baseline: 1.9358x; 1.1392x over previous
#include <cuda_runtime.h>
#include <cuda_bf16.h>
#include <math.h>

#define B 512
#define S 64
#define KNB 8
#define D 16
#define NSTEPS 100
#define NUNITS 128

#define BS   (B*S)        // 32768
#define BSN  (BS*KNB)     // 262144
#define NDIFF (B/2)       // 256 diffusion blocks (2 batches each)

// ---- device scratch (static, allocation-free) ----
__device__ float g_urel[B * 64];
__device__ int   g_e1[BSN];
__device__ int   g_r0[BSN];
__device__ float g_ev0[BS * D];
__device__ int   g_e2[BSN * KNB];
__device__ float g_w [BSN * KNB];
__device__ float g_item[BS * D];
__device__ float g_ab[NSTEPS];
__device__ float g_omb[NSTEPS];
__device__ int   g_cnt[B];

// ---------------------------------------------------------------------------
// K1: hop-0 adjacency gather + ev0 + urel + alpha table + counter reset.
// ---------------------------------------------------------------------------
__global__ __launch_bounds__(256) void k1_kernel(
    const int* __restrict__ click_seq,
    const int* __restrict__ adj_ent, const int* __restrict__ adj_rel,
    const float* __restrict__ ent_emb,
    const float* __restrict__ usr_emb, const float* __restrict__ rel_emb,
    const int* __restrict__ u)
{
    int tid = threadIdx.x;
    int gt = blockIdx.x * 256 + tid;

    if (gt < BSN) {
        int bs = gt >> 3, j = gt & 7;
        int e0 = __ldg(click_seq + bs);
        g_e1[gt] = __ldg(adj_ent + (size_t)e0 * KNB + j);
        g_r0[gt] = __ldg(adj_rel + (size_t)e0 * KNB + j);
        if (j < 4) {
            float4 v = __ldg((const float4*)ent_emb + (size_t)e0 * 4 + j);
            ((float4*)g_ev0)[bs * 4 + j] = v;
        }
    }
    if (gt < B * 64) {
        int b = gt >> 6, r = gt & 63;
        const float* ur = usr_emb + (size_t)__ldg(u + b) * D;
        const float* rr = rel_emb + r * D;
        float s = 0.f;
#pragma unroll
        for (int d = 0; d < D; d++) s += __ldg(ur + d) * __ldg(rr + d);
        g_urel[gt] = s * (1.0f / 16.0f);
    }
    if (gt < B) g_cnt[gt] = 0;
    // alpha schedule (block 0 only)
    if (blockIdx.x == 0) {
        __shared__ float betas[NSTEPS];
        if (tid < NSTEPS) {
            float z = -6.f + 12.f * (float)tid / 99.f;
            betas[tid] = (1.f / (1.f + expf(-z))) * (0.005f - 1e-5f) + 1e-5f;
        }
        __syncthreads();
        if (tid == 0) {
            float ap = 1.f;
            for (int i = 0; i < NSTEPS; i++) {
                ap *= (1.f - betas[i]);
                g_ab[i]  = sqrtf(ap);
                g_omb[i] = sqrtf(1.f - ap);
            }
        }
    }
}

// ---------------------------------------------------------------------------
// K2: thread per (bsn,k). Gathers adj(e1) rows, computes softmax weight w.
// ---------------------------------------------------------------------------
__global__ __launch_bounds__(256) void k2_kernel(
    const int* __restrict__ adj_ent, const int* __restrict__ adj_rel)
{
    int gt = blockIdx.x * 256 + threadIdx.x;
    int bsn = gt >> 3, k = gt & 7;
    int b = bsn >> 9;

    int e1 = __ldg(g_e1 + bsn);
    int e2 = __ldg(adj_ent + (size_t)e1 * KNB + k);
    int r1 = __ldg(adj_rel + (size_t)e1 * KNB + k);

    float s = __ldg(g_urel + b * 64 + r1);
    float m = s;
    m = fmaxf(m, __shfl_xor_sync(0xffffffffu, m, 1));
    m = fmaxf(m, __shfl_xor_sync(0xffffffffu, m, 2));
    m = fmaxf(m, __shfl_xor_sync(0xffffffffu, m, 4));
    float e = expf(s - m);
    float sum = e;
    sum += __shfl_xor_sync(0xffffffffu, sum, 1);
    sum += __shfl_xor_sync(0xffffffffu, sum, 2);
    sum += __shfl_xor_sync(0xffffffffu, sum, 4);

    g_w[gt]  = e / sum;
    g_e2[gt] = e2;
}

// ---------------------------------------------------------------------------
// K3 (single big kernel): blocks [0,NDIFF) = diffusion MLP (2 batches each);
// blocks [NDIFF, NDIFF+BS/8) = gather+aggregate for 8 (b,s) pairs, and the
// last-finishing block of each batch runs the fusion head.
// ---------------------------------------------------------------------------
__global__ __launch_bounds__(256) void k3_kernel(
    const float* __restrict__ ent_emb,
    const float* __restrict__ agg_W, const float* __restrict__ agg_b,
    const float* __restrict__ usr_emb,
    const float* __restrict__ W1, const float* __restrict__ b1,
    const float* __restrict__ W2, const float* __restrict__ b2,
    const float* __restrict__ W3, const float* __restrict__ b3,
    const float* __restrict__ W4, const float* __restrict__ b4,
    const float* __restrict__ se1, const float* __restrict__ se2,
    const float* __restrict__ se3,
    const float* __restrict__ noise_e,
    const float* __restrict__ fc1_W, const float* __restrict__ fc1_b,
    const float* __restrict__ fc2_W, const float* __restrict__ fc2_b,
    const int* __restrict__ u, const int* __restrict__ v,
    const int* __restrict__ t,
    float* __restrict__ out)
{
    int tid = threadIdx.x;

    // ======================= diffusion path =======================
    if (blockIdx.x < NDIFF) {
        __shared__ float xs[2][16], ha[2][128], hb[2][128], p4[2][8][16];
        int bb2 = tid >> 7, tt = tid & 127;
        int b = blockIdx.x * 2 + bb2;
        int tb = __ldg(t + b);
        if (tt < 16)
            xs[bb2][tt] = __ldg(usr_emb + (size_t)__ldg(u + b) * D + tt) * __ldg(g_ab + tb)
                        + __ldg(noise_e + b * D + tt) * __ldg(g_omb + tb);
        __syncthreads();
        // layer 1 (16 -> 128)
        {
            float a = __ldg(b1 + tt) + __ldg(se1 + tb * NUNITS + tt);
#pragma unroll
            for (int d = 0; d < 16; d++)
                a = fmaf(xs[bb2][d], __ldg(W1 + d * NUNITS + tt), a);
            ha[bb2][tt] = fmaxf(a, 0.f);
        }
        __syncthreads();
        // layer 2 (128 -> 128)
        {
            float a0 = 0.f, a1 = 0.f, a2 = 0.f, a3 = 0.f;
#pragma unroll
            for (int i = 0; i < 128; i += 4) {
                a0 = fmaf(ha[bb2][i+0], __ldg(W2 + (i+0) * NUNITS + tt), a0);
                a1 = fmaf(ha[bb2][i+1], __ldg(W2 + (i+1) * NUNITS + tt), a1);
                a2 = fmaf(ha[bb2][i+2], __ldg(W2 + (i+2) * NUNITS + tt), a2);
                a3 = fmaf(ha[bb2][i+3], __ldg(W2 + (i+3) * NUNITS + tt), a3);
            }
            float a = __ldg(b2 + tt) + __ldg(se2 + tb * NUNITS + tt)
                    + ((a0 + a1) + (a2 + a3));
            hb[bb2][tt] = fmaxf(a, 0.f);
        }
        __syncthreads();
        // layer 3 (128 -> 128)
        {
            float a0 = 0.f, a1 = 0.f, a2 = 0.f, a3 = 0.f;
#pragma unroll
            for (int i = 0; i < 128; i += 4) {
                a0 = fmaf(hb[bb2][i+0], __ldg(W3 + (i+0) * NUNITS + tt), a0);
                a1 = fmaf(hb[bb2][i+1], __ldg(W3 + (i+1) * NUNITS + tt), a1);
                a2 = fmaf(hb[bb2][i+2], __ldg(W3 + (i+2) * NUNITS + tt), a2);
                a3 = fmaf(hb[bb2][i+3], __ldg(W3 + (i+3) * NUNITS + tt), a3);
            }
            float a = __ldg(b3 + tt) + __ldg(se3 + tb * NUNITS + tt)
                    + ((a0 + a1) + (a2 + a3));
            ha[bb2][tt] = fmaxf(a, 0.f);
        }
        __syncthreads();
        // layer 4 (128 -> 16), partials over all 128 threads
        {
            int g = tt >> 4, d = tt & 15;
            float a = 0.f;
#pragma unroll
            for (int i = 0; i < 16; i++)
                a = fmaf(ha[bb2][g * 16 + i], __ldg(W4 + (g * 16 + i) * D + d), a);
            p4[bb2][g][d] = a;
        }
        __syncthreads();
        if (tt < 16) {
            float a = __ldg(b4 + tt);
#pragma unroll
            for (int g = 0; g < 8; g++) a += p4[bb2][g][tt];
            out[b * (1 + D) + 1 + tt] = a;
        }
        return;
    }

    // ======================= gather path =======================
    __shared__ float Wm[256], bb[16];
    __shared__ float tmp1s[8][8][17];
    __shared__ float ev1s[8][8][17];
    __shared__ float out1s[8][8][17];
    __shared__ float ev0s[8][16];
    __shared__ float p0s[8][8];
    __shared__ float t0s[8][17];
    __shared__ float tfs[8][17];
    __shared__ int   headflag;

    int gb  = blockIdx.x - NDIFF;
    int bsl = tid >> 5, n = (tid >> 2) & 7, q = tid & 3;
    int bs  = gb * 8 + bsl;
    int bsn = bs * KNB + n;
    int b   = bs >> 6;
    int bq  = (gb * 8) >> 6;     // batch owning all 8 bs of this block

    Wm[tid] = __ldg(agg_W + tid);
    if (tid < 16) bb[tid] = __ldg(agg_b + tid);

    int4   ea = __ldg((const int4*)g_e2 + bsn * 2);
    int4   eb = __ldg((const int4*)g_e2 + bsn * 2 + 1);
    float4 wa = __ldg((const float4*)g_w + bsn * 2);
    float4 wb = __ldg((const float4*)g_w + bsn * 2 + 1);
    int e1 = __ldg(g_e1 + bsn);

    const float4* E = (const float4*)ent_emb;
    float4 v0 = __ldg(E + (size_t)ea.x * 4 + q);
    float4 v1 = __ldg(E + (size_t)ea.y * 4 + q);
    float4 v2 = __ldg(E + (size_t)ea.z * 4 + q);
    float4 v3 = __ldg(E + (size_t)ea.w * 4 + q);
    float4 v4 = __ldg(E + (size_t)eb.x * 4 + q);
    float4 v5 = __ldg(E + (size_t)eb.y * 4 + q);
    float4 v6 = __ldg(E + (size_t)eb.z * 4 + q);
    float4 v7 = __ldg(E + (size_t)eb.w * 4 + q);
    float4 e1v = __ldg(E + (size_t)e1 * 4 + q);

    float4 acc;
    acc.x = wa.x*v0.x + wa.y*v1.x + wa.z*v2.x + wa.w*v3.x
          + wb.x*v4.x + wb.y*v5.x + wb.z*v6.x + wb.w*v7.x;
    acc.y = wa.x*v0.y + wa.y*v1.y + wa.z*v2.y + wa.w*v3.y
          + wb.x*v4.y + wb.y*v5.y + wb.z*v6.y + wb.w*v7.y;
    acc.z = wa.x*v0.z + wa.y*v1.z + wa.z*v2.z + wa.w*v3.z
          + wb.x*v4.z + wb.y*v5.z + wb.z*v6.z + wb.w*v7.z;
    acc.w = wa.x*v0.w + wa.y*v1.w + wa.z*v2.w + wa.w*v3.w
          + wb.x*v4.w + wb.y*v5.w + wb.z*v6.w + wb.w*v7.w;

    int qq = q * 4;
    tmp1s[bsl][n][qq+0] = e1v.x + acc.x;
    tmp1s[bsl][n][qq+1] = e1v.y + acc.y;
    tmp1s[bsl][n][qq+2] = e1v.z + acc.z;
    tmp1s[bsl][n][qq+3] = e1v.w + acc.w;
    ev1s[bsl][n][qq+0] = e1v.x;
    ev1s[bsl][n][qq+1] = e1v.y;
    ev1s[bsl][n][qq+2] = e1v.z;
    ev1s[bsl][n][qq+3] = e1v.w;

    if (tid < 128) {
        int bl = tid >> 4, d = tid & 15;
        ev0s[bl][d] = __ldg(g_ev0 + (size_t)(gb * 8 + bl) * 16 + d);
    }

    // hop-0 softmax weights p0
    {
        int r0 = __ldg(g_r0 + bsn);
        float s = __ldg(g_urel + b * 64 + r0);
        float m = s;
        m = fmaxf(m, __shfl_xor_sync(0xffffffffu, m, 4));
        m = fmaxf(m, __shfl_xor_sync(0xffffffffu, m, 8));
        m = fmaxf(m, __shfl_xor_sync(0xffffffffu, m, 16));
        float e = expf(s - m);
        float sum = e;
        sum += __shfl_xor_sync(0xffffffffu, sum, 4);
        sum += __shfl_xor_sync(0xffffffffu, sum, 8);
        sum += __shfl_xor_sync(0xffffffffu, sum, 16);
        if (q == 0) p0s[bsl][n] = e / sum;
    }
    __syncthreads();

    // hop1 linear + sigmoid (4 outputs / thread); t0 partial on tid<128
#pragma unroll
    for (int j = 0; j < 4; j++) {
        int o = tid + 256 * j;
        int bl = o >> 7, n2 = (o >> 4) & 7, dp = o & 15;
        float a = bb[dp];
#pragma unroll
        for (int d = 0; d < 16; d++)
            a = fmaf(tmp1s[bl][n2][d], Wm[d * 16 + dp], a);
        out1s[bl][n2][dp] = 1.f / (1.f + expf(-a));
    }
    if (tid < 128) {
        int bl = tid >> 4, d = tid & 15;
        float t0 = ev0s[bl][d];
#pragma unroll
        for (int k = 0; k < 8; k++)
            t0 = fmaf(p0s[bl][k], ev1s[bl][k][d], t0);
        t0s[bl][d] = t0;
    }
    __syncthreads();

    if (tid < 128) {
        int bl = tid >> 4, d = tid & 15;
        float a = bb[d];
#pragma unroll
        for (int d2 = 0; d2 < 16; d2++)
            a = fmaf(t0s[bl][d2], Wm[d2 * 16 + d], a);
        float o0 = 1.f / (1.f + expf(-a));
        float tf = o0;
#pragma unroll
        for (int k = 0; k < 8; k++)
            tf = fmaf(p0s[bl][k], out1s[bl][k][d], tf);
        tfs[bl][d] = tf;
    }
    __syncthreads();

    if (tid < 128) {
        int bl = tid >> 4, d = tid & 15;
        float a = bb[d];
#pragma unroll
        for (int d2 = 0; d2 < 16; d2++)
            a = fmaf(tfs[bl][d2], Wm[d2 * 16 + d], a);
        g_item[(size_t)(gb * 8 + bl) * 16 + d] = fmaxf(tanhf(a), 0.f);
    }

    // -------- last-block-per-batch fusion head --------
    if (tid == 0) {
        __threadfence();
        int old = atomicAdd(&g_cnt[bq], 1);
        headflag = (old == 7);
    }
    __syncthreads();
    if (!headflag) return;
    __threadfence();

    __shared__ float ps[8][16], pm[8][16], fus[32], hh[64];
    if (tid < 128) {
        int d = tid & 15, sc = tid >> 4;
        float s = 0.f, m = -1e30f;
#pragma unroll
        for (int j = 0; j < 8; j++) {
            float vv = g_item[((size_t)bq * S + sc * 8 + j) * D + d];
            s += vv;
            m = fmaxf(m, vv);
        }
        ps[sc][d] = s;
        pm[sc][d] = m;
    }
    __syncthreads();
    if (tid < 16) {
        float s = 0.f, m = -1e30f;
#pragma unroll
        for (int c = 0; c < 8; c++) { s += ps[c][tid]; m = fmaxf(m, pm[c][tid]); }
        fus[tid]      = fmaxf(s, 0.f);
        fus[16 + tid] = fmaxf(m, 0.f);
    }
    __syncthreads();
    if (tid < 64) {
        float a = __ldg(fc1_b + tid);
#pragma unroll
        for (int i = 0; i < 32; i++)
            a = fmaf(fus[i], __ldg(fc1_W + i * 64 + tid), a);
        hh[tid] = fmaxf(a, 0.f);
    }
    __syncthreads();
    if (tid < 16) {
        float a = __ldg(fc2_b + tid);
#pragma unroll
        for (int i = 0; i < 64; i++)
            a = fmaf(hh[i], __ldg(fc2_W + i * D + tid), a);
        float f = fmaxf(a, 0.f);
        float p = f * __ldg(ent_emb + (size_t)__ldg(v + bq) * D + tid);
        p += __shfl_xor_sync(0xffffu, p, 8);
        p += __shfl_xor_sync(0xffffu, p, 4);
        p += __shfl_xor_sync(0xffffu, p, 2);
        p += __shfl_xor_sync(0xffffu, p, 1);
        if (tid == 0)
            out[bq * (1 + D)] = 1.f / (1.f + expf(-p));
    }
}

// ---------------------------------------------------------------------------
extern "C" void kernel_launch(void* const* d_in, const int* in_sizes, int n_in,
                              void* d_out, int out_size)
{
    const float* usr_emb  = (const float*)d_in[0];
    const float* ent_emb  = (const float*)d_in[1];
    const float* rel_emb  = (const float*)d_in[2];
    const float* agg_W    = (const float*)d_in[3];
    const float* agg_b    = (const float*)d_in[4];
    const float* fc1_W    = (const float*)d_in[5];
    const float* fc1_b    = (const float*)d_in[6];
    const float* fc2_W    = (const float*)d_in[7];
    const float* fc2_b    = (const float*)d_in[8];
    const float* mlp_W1   = (const float*)d_in[9];
    const float* mlp_b1   = (const float*)d_in[10];
    const float* mlp_W2   = (const float*)d_in[11];
    const float* mlp_b2   = (const float*)d_in[12];
    const float* mlp_W3   = (const float*)d_in[13];
    const float* mlp_b3   = (const float*)d_in[14];
    const float* mlp_W4   = (const float*)d_in[15];
    const float* mlp_b4   = (const float*)d_in[16];
    const float* se1      = (const float*)d_in[17];
    const float* se2      = (const float*)d_in[18];
    const float* se3      = (const float*)d_in[19];
    const float* noise_e  = (const float*)d_in[20];
    const int*   u        = (const int*)d_in[21];
    const int*   v        = (const int*)d_in[22];
    const int*   click    = (const int*)d_in[23];
    const int*   adj_ent  = (const int*)d_in[24];
    const int*   adj_rel  = (const int*)d_in[25];
    const int*   t        = (const int*)d_in[26];
    float* out = (float*)d_out;

    k1_kernel<<<(BSN + 255) / 256, 256>>>(click, adj_ent, adj_rel, ent_emb,
                                          usr_emb, rel_emb, u);
    k2_kernel<<<(BSN * KNB) / 256, 256>>>(adj_ent, adj_rel);
    k3_kernel<<<NDIFF + BS / 8, 256>>>(ent_emb, agg_W, agg_b, usr_emb,
                                       mlp_W1, mlp_b1, mlp_W2, mlp_b2,
                                       mlp_W3, mlp_b3, mlp_W4, mlp_b4,
                                       se1, se2, se3, noise_e,
                                       fc1_W, fc1_b, fc2_W, fc2_b,
                                       u, v, t, out);
}